// round 1
// baseline (speedup 1.0000x reference)
#include <cuda_runtime.h>
#include <math.h>

#define NN   50000
#define EE   400000
#define EP   450000     // EE + NN self loops
#define IN_F 128
#define HIDF 16
#define H    11
#define HC   176        // H * HIDF
#define G    64
#define OUTF 32
#define NCF  10
#define PARTS 8

// ---------------- scratch (static device globals; no allocation) ----------------
__device__ float    g_h[(size_t)NN * HC];
__device__ float    g_buf[(size_t)NN * HC];     // conv output / agg buffer
__device__ float    g_xl[(size_t)NN * HC];
__device__ float    g_xr[(size_t)NN * HC];
__device__ float    g_alpha[(size_t)EP * H];
__device__ unsigned g_amax[(size_t)NN * H];
__device__ float    g_den[(size_t)NN * H];
__device__ float    g_sum[G * HC];
__device__ float    g_sq[G * HC];
__device__ float    g_mean[G * HC];
__device__ float    g_rstd[G * HC];
__device__ int      g_start[G + 1];
__device__ float    g_out16[(size_t)NN * HIDF];

// ---------------- helpers ----------------
__device__ __forceinline__ unsigned encf(float f) {
    unsigned u = __float_as_uint(f);
    return (u & 0x80000000u) ? ~u : (u | 0x80000000u);
}
__device__ __forceinline__ float decf(unsigned u) {
    return (u & 0x80000000u) ? __uint_as_float(u ^ 0x80000000u) : __uint_as_float(~u);
}

// ---------------- segment boundaries ----------------
__global__ void seg_mark(const int* __restrict__ batch, int* __restrict__ start) {
    int i = blockIdx.x * blockDim.x + threadIdx.x;
    if (i >= NN) return;
    if (i == 0 || batch[i] != batch[i - 1]) start[batch[i]] = i;
}
__global__ void seg_fix(int* start) {
    if (threadIdx.x == 0) {
        start[G] = NN;
        for (int g = G - 1; g >= 0; g--)
            if (start[g] < 0) start[g] = start[g + 1];
    }
}

// ---------------- tiled SGEMM: C[M,N] = A[M,K] @ B[K,N] (+ bias) ----------------
#define BM 64
#define BN 64
#define BK 16
__global__ void gemm_bias(const float* __restrict__ A, const float* __restrict__ B,
                          const float* __restrict__ bias, float* __restrict__ C,
                          int M, int N, int K) {
    __shared__ float As[BM][BK + 1];
    __shared__ float Bs[BK][BN + 1];
    int tid = threadIdx.x;
    int tx = tid & 15, ty = tid >> 4;
    int rowBase = blockIdx.y * BM;
    int colBase = blockIdx.x * BN;
    float acc[4][4] = {};
    for (int k0 = 0; k0 < K; k0 += BK) {
        #pragma unroll
        for (int t = tid; t < BM * BK; t += 256) {
            int r = t / BK, c = t % BK;
            int gr = rowBase + r, gc = k0 + c;
            As[r][c] = (gr < M && gc < K) ? A[(size_t)gr * K + gc] : 0.f;
        }
        #pragma unroll
        for (int t = tid; t < BK * BN; t += 256) {
            int r = t / BN, c = t % BN;
            int gr = k0 + r, gc = colBase + c;
            Bs[r][c] = (gr < K && gc < N) ? B[(size_t)gr * N + gc] : 0.f;
        }
        __syncthreads();
        #pragma unroll
        for (int k = 0; k < BK; k++) {
            float a[4], b[4];
            #pragma unroll
            for (int i = 0; i < 4; i++) a[i] = As[ty * 4 + i][k];
            #pragma unroll
            for (int j = 0; j < 4; j++) b[j] = Bs[k][tx * 4 + j];
            #pragma unroll
            for (int i = 0; i < 4; i++)
                #pragma unroll
                for (int j = 0; j < 4; j++) acc[i][j] += a[i] * b[j];
        }
        __syncthreads();
    }
    #pragma unroll
    for (int i = 0; i < 4; i++) {
        int gr = rowBase + ty * 4 + i;
        if (gr >= M) continue;
        #pragma unroll
        for (int j = 0; j < 4; j++) {
            int gc = colBase + tx * 4 + j;
            if (gc >= N) continue;
            C[(size_t)gr * N + gc] = acc[i][j] + (bias ? bias[gc] : 0.f);
        }
    }
}

// ---------------- GraphNorm ----------------
__global__ void gn_stats_part(const float* __restrict__ x) {
    int g = blockIdx.x;
    int part = blockIdx.y;
    int f = threadIdx.x;
    if (f >= HC) return;
    int s0 = g_start[g], s1 = g_start[g + 1];
    float sum = 0.f, sq = 0.f;
    for (int n = s0 + part; n < s1; n += PARTS) {
        float v = x[(size_t)n * HC + f];
        sum += v;
        sq += v * v;
    }
    atomicAdd(&g_sum[g * HC + f], sum);
    atomicAdd(&g_sq[g * HC + f], sq);
}
__global__ void gn_finalize(const float* __restrict__ gn_ms, int layer) {
    int idx = blockIdx.x * blockDim.x + threadIdx.x;
    if (idx >= G * HC) return;
    int g = idx / HC, f = idx - g * HC;
    float cnt = (float)max(g_start[g + 1] - g_start[g], 1);
    float m = g_sum[idx] / cnt;
    float ms = gn_ms[layer * HC + f];
    float var = g_sq[idx] / cnt + m * m * (ms * ms - 2.f * ms);
    g_mean[idx] = m;
    g_rstd[idx] = 1.f / sqrtf(var + 1e-5f);
}
__global__ void gn_norm_relu(const float* __restrict__ x, float* __restrict__ y,
                             const float* __restrict__ gn_w, const float* __restrict__ gn_b,
                             const float* __restrict__ gn_ms, int layer,
                             const int* __restrict__ batch) {
    int idx = blockIdx.x * blockDim.x + threadIdx.x;
    if (idx >= NN * HC) return;
    int n = idx / HC, f = idx - n * HC;
    int g = batch[n];
    float v = (x[idx] - gn_ms[layer * HC + f] * g_mean[g * HC + f]) * g_rstd[g * HC + f];
    v = v * gn_w[layer * HC + f] + gn_b[layer * HC + f];
    y[idx] = fmaxf(v, 0.f);
}

// ---------------- GATv2 edge kernels ----------------
__global__ void attn_alpha(const int* __restrict__ ei, const float* __restrict__ att) {
    int idx = blockIdx.x * blockDim.x + threadIdx.x;
    if (idx >= EP * H) return;
    int e = idx / H;
    int h = idx - e * H;
    int s, d;
    if (e < EE) { s = ei[e]; d = ei[EE + e]; }
    else        { s = e - EE; d = s; }
    const float4* pl = reinterpret_cast<const float4*>(g_xl + (size_t)s * HC + h * HIDF);
    const float4* pr = reinterpret_cast<const float4*>(g_xr + (size_t)d * HC + h * HIDF);
    const float4* pa = reinterpret_cast<const float4*>(att + h * HIDF);
    float acc = 0.f;
    #pragma unroll
    for (int i = 0; i < 4; i++) {
        float4 l = pl[i], r = pr[i], a = pa[i];
        float v;
        v = l.x + r.x; v = v > 0.f ? v : 0.2f * v; acc += v * a.x;
        v = l.y + r.y; v = v > 0.f ? v : 0.2f * v; acc += v * a.y;
        v = l.z + r.z; v = v > 0.f ? v : 0.2f * v; acc += v * a.z;
        v = l.w + r.w; v = v > 0.f ? v : 0.2f * v; acc += v * a.w;
    }
    g_alpha[idx] = acc;
    atomicMax(&g_amax[(size_t)d * H + h], encf(acc));
}

__global__ void attn_exp(const int* __restrict__ ei) {
    int idx = blockIdx.x * blockDim.x + threadIdx.x;
    if (idx >= EP * H) return;
    int e = idx / H;
    int h = idx - e * H;
    int d = (e < EE) ? ei[EE + e] : (e - EE);
    float m = decf(g_amax[(size_t)d * H + h]);
    float ex = expf(g_alpha[idx] - m);
    g_alpha[idx] = ex;
    atomicAdd(&g_den[(size_t)d * H + h], ex);
}

__global__ void attn_agg(const int* __restrict__ ei, float* __restrict__ out) {
    int idx = blockIdx.x * blockDim.x + threadIdx.x;
    if (idx >= EP * H) return;
    int e = idx / H;
    int h = idx - e * H;
    int s, d;
    if (e < EE) { s = ei[e]; d = ei[EE + e]; }
    else        { s = e - EE; d = s; }
    float a = g_alpha[idx] / (g_den[(size_t)d * H + h] + 1e-16f);
    const float4* pl = reinterpret_cast<const float4*>(g_xl + (size_t)s * HC + h * HIDF);
    float* po = out + (size_t)d * HC + h * HIDF;
    #pragma unroll
    for (int i = 0; i < 4; i++) {
        float4 l = pl[i];
        atomicAdd(po + i * 4 + 0, l.x * a);
        atomicAdd(po + i * 4 + 1, l.y * a);
        atomicAdd(po + i * 4 + 2, l.z * a);
        atomicAdd(po + i * 4 + 3, l.w * a);
    }
}

// ---------------- conv5 head mean + relu ----------------
__global__ void head_mean_relu() {
    int idx = blockIdx.x * blockDim.x + threadIdx.x;
    if (idx >= NN * HIDF) return;
    int n = idx / HIDF, c = idx - n * HIDF;
    float s = 0.f;
    #pragma unroll
    for (int h = 0; h < H; h++) s += g_buf[(size_t)n * HC + h * HIDF + c];
    g_out16[idx] = fmaxf(g_out16[idx] + s * (1.f / (float)H), 0.f);
}

// ---------------- final fused MLP: 16 -> 16 -> 32 -> 10 ----------------
__global__ void mlp(const float* __restrict__ Wo1, const float* __restrict__ bo1,
                    const float* __restrict__ Wo2, const float* __restrict__ bo2,
                    const float* __restrict__ Wc,  const float* __restrict__ bc,
                    float* __restrict__ out) {
    __shared__ float w1[16 * 16], w2[16 * 32], w3[32 * 10], b1[16], b2[32], b3[10];
    int tid = threadIdx.x;
    if (tid < 256) w1[tid] = Wo1[tid];
    for (int t = tid; t < 512; t += blockDim.x) w2[t] = Wo2[t];
    for (int t = tid; t < 320; t += blockDim.x) w3[t] = Wc[t];
    if (tid < 16) b1[tid] = bo1[tid];
    if (tid < 32) b2[tid] = bo2[tid];
    if (tid < 10) b3[tid] = bc[tid];
    __syncthreads();
    int n = blockIdx.x * blockDim.x + tid;
    if (n >= NN) return;
    float a[16];
    #pragma unroll
    for (int i = 0; i < 16; i++) a[i] = g_out16[(size_t)n * 16 + i];
    float t1[16];
    #pragma unroll
    for (int j = 0; j < 16; j++) {
        float acc = b1[j];
        #pragma unroll
        for (int i = 0; i < 16; i++) acc += a[i] * w1[i * 16 + j];
        t1[j] = fmaxf(acc, 0.f);
    }
    float t2[32];
    #pragma unroll
    for (int j = 0; j < 32; j++) {
        float acc = b2[j];
        #pragma unroll
        for (int i = 0; i < 16; i++) acc += t1[i] * w2[i * 32 + j];
        t2[j] = fmaxf(acc, 0.f);
    }
    #pragma unroll
    for (int j = 0; j < 10; j++) {
        float acc = b3[j];
        #pragma unroll
        for (int k = 0; k < 32; k++) acc += t2[k] * w3[k * 10 + j];
        out[(size_t)n * 10 + j] = acc;
    }
}

// ---------------- host launch ----------------
extern "C" void kernel_launch(void* const* d_in, const int* in_sizes, int n_in,
                              void* d_out, int out_size) {
    const float* x        = (const float*)d_in[0];
    const int*   ei       = (const int*)d_in[1];
    const int*   batch    = (const int*)d_in[2];
    const float* W_pre    = (const float*)d_in[3];
    const float* b_pre    = (const float*)d_in[4];
    const float* gn_w     = (const float*)d_in[5];
    const float* gn_b     = (const float*)d_in[6];
    const float* gn_ms    = (const float*)d_in[7];
    const float* conv_Wl  = (const float*)d_in[8];
    const float* conv_Wr  = (const float*)d_in[9];
    const float* conv_att = (const float*)d_in[10];
    const float* conv_b   = (const float*)d_in[11];
    const float* conv_Wres= (const float*)d_in[12];
    const float* c5_Wl    = (const float*)d_in[13];
    const float* c5_Wr    = (const float*)d_in[14];
    const float* c5_att   = (const float*)d_in[15];
    const float* c5_b     = (const float*)d_in[16];
    const float* c5_Wres  = (const float*)d_in[17];
    const float* W_o1     = (const float*)d_in[18];
    const float* b_o1     = (const float*)d_in[19];
    const float* W_o2     = (const float*)d_in[20];
    const float* b_o2     = (const float*)d_in[21];
    const float* W_cls    = (const float*)d_in[22];
    const float* b_cls    = (const float*)d_in[23];
    float* out = (float*)d_out;

    float *p_h, *p_buf, *p_xl, *p_xr, *p_den, *p_sum, *p_sq, *p_out16;
    unsigned* p_amax;
    int* p_start;
    cudaGetSymbolAddress((void**)&p_h, g_h);
    cudaGetSymbolAddress((void**)&p_buf, g_buf);
    cudaGetSymbolAddress((void**)&p_xl, g_xl);
    cudaGetSymbolAddress((void**)&p_xr, g_xr);
    cudaGetSymbolAddress((void**)&p_den, g_den);
    cudaGetSymbolAddress((void**)&p_sum, g_sum);
    cudaGetSymbolAddress((void**)&p_sq, g_sq);
    cudaGetSymbolAddress((void**)&p_out16, g_out16);
    cudaGetSymbolAddress((void**)&p_amax, g_amax);
    cudaGetSymbolAddress((void**)&p_start, g_start);

    // segment boundaries
    cudaMemsetAsync(p_start, 0xFF, (G + 1) * sizeof(int));
    seg_mark<<<(NN + 255) / 256, 256>>>(batch, p_start);
    seg_fix<<<1, 32>>>(p_start);

    auto gemm = [&](const float* A, const float* B, const float* bias, float* C,
                    int M, int Ncols, int K) {
        dim3 grid((Ncols + BN - 1) / BN, (M + BM - 1) / BM);
        gemm_bias<<<grid, 256>>>(A, B, bias, C, M, Ncols, K);
    };
    auto graphnorm = [&](const float* src, float* dst, int layer) {
        cudaMemsetAsync(p_sum, 0, G * HC * sizeof(float));
        cudaMemsetAsync(p_sq, 0, G * HC * sizeof(float));
        dim3 sgrid(G, PARTS);
        gn_stats_part<<<sgrid, 192>>>(src);
        gn_finalize<<<(G * HC + 255) / 256, 256>>>(gn_ms, layer);
        gn_norm_relu<<<(NN * HC + 255) / 256, 256>>>(src, dst, gn_w, gn_b, gn_ms, layer, batch);
    };

    const int attBlocks = (EP * H + 255) / 256;

    // pre-layer
    gemm(x, W_pre, b_pre, p_buf, NN, HC, IN_F);
    graphnorm(p_buf, p_h, 0);

    // conv layers 1..4 (concat=True)
    for (int L = 0; L < 4; L++) {
        gemm(p_h, conv_Wl + (size_t)L * HC * HC, nullptr, p_xl, NN, HC, HC);
        gemm(p_h, conv_Wr + (size_t)L * HC * HC, nullptr, p_xr, NN, HC, HC);
        gemm(p_h, conv_Wres + (size_t)L * HC * HC, conv_b + L * HC, p_buf, NN, HC, HC);
        cudaMemsetAsync(p_amax, 0, (size_t)NN * H * sizeof(unsigned));
        cudaMemsetAsync(p_den, 0, (size_t)NN * H * sizeof(float));
        attn_alpha<<<attBlocks, 256>>>(ei, conv_att + L * H * HIDF);
        attn_exp<<<attBlocks, 256>>>(ei);
        attn_agg<<<attBlocks, 256>>>(ei, p_buf);
        graphnorm(p_buf, p_h, L + 1);
    }

    // conv5 (concat=False -> mean over heads, out dim HIDF)
    gemm(p_h, c5_Wl, nullptr, p_xl, NN, HC, HC);
    gemm(p_h, c5_Wr, nullptr, p_xr, NN, HC, HC);
    gemm(p_h, c5_Wres, c5_b, p_out16, NN, HIDF, HC);
    cudaMemsetAsync(p_amax, 0, (size_t)NN * H * sizeof(unsigned));
    cudaMemsetAsync(p_den, 0, (size_t)NN * H * sizeof(float));
    cudaMemsetAsync(p_buf, 0, (size_t)NN * HC * sizeof(float));
    attn_alpha<<<attBlocks, 256>>>(ei, c5_att);
    attn_exp<<<attBlocks, 256>>>(ei);
    attn_agg<<<attBlocks, 256>>>(ei, p_buf);
    head_mean_relu<<<(NN * HIDF + 255) / 256, 256>>>();

    // final MLP
    mlp<<<(NN + 255) / 256, 256>>>(W_o1, b_o1, W_o2, b_o2, W_cls, b_cls, out);
}

// round 2
// speedup vs baseline: 2.6968x; 2.6968x over previous
#include <cuda_runtime.h>
#include <cuda_bf16.h>
#include <math.h>

#define NN   50000
#define EE   400000
#define EP   450000     // EE + NN self loops
#define IN_F 128
#define HIDF 16
#define H    11
#define HC   176        // H * HIDF
#define G    64
#define OUTF 32
#define NCF  10
#define PARTS 32

// weight-split offsets (elements)
#define OFF_PRE   0
#define SZ_PRE    (IN_F * HC)                 // 22528
#define OFF_WL    (OFF_PRE + SZ_PRE)
#define SZ_W      (HC * HC)                   // 30976
#define OFF_WR    (OFF_WL + 4 * SZ_W)
#define OFF_WRES  (OFF_WR + 4 * SZ_W)
#define OFF_C5L   (OFF_WRES + 4 * SZ_W)
#define OFF_C5R   (OFF_C5L + SZ_W)
#define OFF_C5RES (OFF_C5R + SZ_W)
#define SZ_C5RES  (HC * HIDF)                 // 2816
#define W_TOTAL   (OFF_C5RES + SZ_C5RES)      // 459008

// ---------------- scratch ----------------
__device__ float    g_h[(size_t)NN * HC];
__device__ float    g_buf[(size_t)NN * HC];
__device__ float    g_xl[(size_t)NN * HC];
__device__ float    g_xr[(size_t)NN * HC];
__device__ float    g_sum[G * HC];
__device__ float    g_sq[G * HC];
__device__ float    g_mean[G * HC];
__device__ float    g_rstd[G * HC];
__device__ int      g_start[G + 1];
__device__ float    g_out16[(size_t)NN * HIDF];
__device__ __nv_bfloat16 g_wh[W_TOTAL];
__device__ __nv_bfloat16 g_wl[W_TOTAL];
__device__ int      g_deg[NN];
__device__ int      g_rowptr[NN + 1];
__device__ int      g_cursor[NN];
__device__ int      g_csr[EP];
__device__ int      g_bsum[256];
__device__ int      g_boff[256];

// ---------------- segment boundaries ----------------
__global__ void seg_mark(const int* __restrict__ batch, int* __restrict__ start) {
    int i = blockIdx.x * blockDim.x + threadIdx.x;
    if (i >= NN) return;
    if (i == 0 || batch[i] != batch[i - 1]) start[batch[i]] = i;
}
__global__ void seg_fix(int* start) {
    if (threadIdx.x == 0) {
        start[G] = NN;
        for (int g = G - 1; g >= 0; g--)
            if (start[g] < 0) start[g] = start[g + 1];
    }
}

// ---------------- CSR build ----------------
__global__ void deg_count(const int* __restrict__ ei) {
    int e = blockIdx.x * blockDim.x + threadIdx.x;
    if (e >= EP) return;
    int d = (e < EE) ? ei[EE + e] : (e - EE);
    atomicAdd(&g_deg[d], 1);
}
#define SCAN_B 256
__global__ void scan1(const int* __restrict__ in, int* __restrict__ out,
                      int* __restrict__ bsum, int n) {
    __shared__ int sh[SCAN_B];
    int i = blockIdx.x * SCAN_B + threadIdx.x;
    int v = (i < n) ? in[i] : 0;
    sh[threadIdx.x] = v;
    __syncthreads();
    for (int off = 1; off < SCAN_B; off <<= 1) {
        int t = (threadIdx.x >= off) ? sh[threadIdx.x - off] : 0;
        __syncthreads();
        sh[threadIdx.x] += t;
        __syncthreads();
    }
    if (i < n) out[i] = sh[threadIdx.x] - v;  // exclusive
    if (threadIdx.x == SCAN_B - 1 && bsum) bsum[blockIdx.x] = sh[threadIdx.x];
}
__global__ void scan_add(int* __restrict__ out, const int* __restrict__ boff, int n) {
    int i = blockIdx.x * SCAN_B + threadIdx.x;
    if (i < n) out[i] += boff[blockIdx.x];
}
__global__ void set_tail(int* rowptr) { if (threadIdx.x == 0) rowptr[NN] = EP; }
__global__ void csr_scatter(const int* __restrict__ ei) {
    int e = blockIdx.x * blockDim.x + threadIdx.x;
    if (e >= EP) return;
    int s, d;
    if (e < EE) { s = ei[e]; d = ei[EE + e]; }
    else        { s = e - EE; d = s; }
    int pos = atomicAdd(&g_cursor[d], 1);
    g_csr[pos] = s;
}

// ---------------- weight split fp32 -> bf16 hi/lo ----------------
__global__ void wsplit(const float* __restrict__ w, __nv_bfloat16* __restrict__ wh,
                       __nv_bfloat16* __restrict__ wl, int n) {
    int i = blockIdx.x * blockDim.x + threadIdx.x;
    if (i >= n) return;
    float x = w[i];
    __nv_bfloat16 h = __float2bfloat16(x);
    wh[i] = h;
    wl[i] = __float2bfloat16(x - __bfloat162float(h));
}

// ---------------- BF16x3 tensor-core GEMM ----------------
// C[M,N] = A[M,K](fp32) @ W[K,N](bf16 hi+lo) (+bias)
#define GBM 128
#define GBN 64
#define GBK 32
#define GST 40   // halves per smem row (32 + 8 pad)

__device__ __forceinline__ void mma16816(float* c, const unsigned* a, const unsigned* b) {
    asm volatile(
        "mma.sync.aligned.m16n8k16.row.col.f32.bf16.bf16.f32 "
        "{%0,%1,%2,%3}, {%4,%5,%6,%7}, {%8,%9}, {%0,%1,%2,%3};\n"
        : "+f"(c[0]), "+f"(c[1]), "+f"(c[2]), "+f"(c[3])
        : "r"(a[0]), "r"(a[1]), "r"(a[2]), "r"(a[3]), "r"(b[0]), "r"(b[1]));
}

__global__ __launch_bounds__(256) void gemm3x(
    const float* __restrict__ A, const __nv_bfloat16* __restrict__ Wh,
    const __nv_bfloat16* __restrict__ Wl, const float* __restrict__ bias,
    float* __restrict__ C, int M, int N, int K) {
    __shared__ __nv_bfloat16 Ash[GBM * GST];
    __shared__ __nv_bfloat16 Asl[GBM * GST];
    __shared__ __nv_bfloat16 Bsh[GBN * GST];
    __shared__ __nv_bfloat16 Bsl[GBN * GST];

    int tid = threadIdx.x;
    int wid = tid >> 5, lane = tid & 31;
    int m0 = blockIdx.y * GBM, n0 = blockIdx.x * GBN;
    int wm = (wid >> 1) * 32;   // warp row offset (4 warps in m)
    int wn = (wid & 1) * 32;    // warp col offset (2 warps in n)

    float c[2][4][4];
    #pragma unroll
    for (int i = 0; i < 2; i++)
        #pragma unroll
        for (int j = 0; j < 4; j++)
            #pragma unroll
            for (int k = 0; k < 4; k++) c[i][j][k] = 0.f;

    for (int k0 = 0; k0 < K; k0 += GBK) {
        // ---- load & split A tile: 128 x 32 fp32 ----
        #pragma unroll
        for (int it = 0; it < 4; it++) {
            int f = tid + it * 256;          // float4 index 0..1023
            int row = f >> 3;
            int c4 = f & 7;
            int gr = m0 + row, gk = k0 + c4 * 4;
            float4 v = make_float4(0.f, 0.f, 0.f, 0.f);
            if (gr < M) {
                const float* ap = A + (size_t)gr * K + gk;
                if (gk + 3 < K) v = *reinterpret_cast<const float4*>(ap);
                else {
                    if (gk + 0 < K) v.x = ap[0];
                    if (gk + 1 < K) v.y = ap[1];
                    if (gk + 2 < K) v.z = ap[2];
                    if (gk + 3 < K) v.w = ap[3];
                }
            }
            int sb = row * GST + c4 * 4;
            float vv[4] = {v.x, v.y, v.z, v.w};
            #pragma unroll
            for (int j = 0; j < 4; j++) {
                __nv_bfloat16 hh = __float2bfloat16(vv[j]);
                Ash[sb + j] = hh;
                Asl[sb + j] = __float2bfloat16(vv[j] - __bfloat162float(hh));
            }
        }
        // ---- load B tile: 32(k) x 64(n), stored transposed [n][k] ----
        #pragma unroll
        for (int it = 0; it < 8; it++) {
            int f = tid + it * 256;          // 0..2047
            int kk = f >> 6, nn = f & 63;
            int gk = k0 + kk, gn = n0 + nn;
            __nv_bfloat16 vh = __float2bfloat16(0.f), vl = vh;
            if (gk < K && gn < N) {
                vh = Wh[(size_t)gk * N + gn];
                vl = Wl[(size_t)gk * N + gn];
            }
            Bsh[nn * GST + kk] = vh;
            Bsl[nn * GST + kk] = vl;
        }
        __syncthreads();

        int r = lane >> 2, cq = (lane & 3) * 2;
        #pragma unroll
        for (int ks = 0; ks < GBK; ks += 16) {
            unsigned ah[2][4], al[2][4], bh[4][2], bl[4][2];
            #pragma unroll
            for (int mf = 0; mf < 2; mf++) {
                int base = wm + mf * 16;
                const __nv_bfloat16* ph = Ash;
                const __nv_bfloat16* pl = Asl;
                int i0 = (base + r) * GST + ks + cq;
                int i1 = (base + r + 8) * GST + ks + cq;
                ah[mf][0] = *reinterpret_cast<const unsigned*>(ph + i0);
                ah[mf][1] = *reinterpret_cast<const unsigned*>(ph + i1);
                ah[mf][2] = *reinterpret_cast<const unsigned*>(ph + i0 + 8);
                ah[mf][3] = *reinterpret_cast<const unsigned*>(ph + i1 + 8);
                al[mf][0] = *reinterpret_cast<const unsigned*>(pl + i0);
                al[mf][1] = *reinterpret_cast<const unsigned*>(pl + i1);
                al[mf][2] = *reinterpret_cast<const unsigned*>(pl + i0 + 8);
                al[mf][3] = *reinterpret_cast<const unsigned*>(pl + i1 + 8);
            }
            #pragma unroll
            for (int nf = 0; nf < 4; nf++) {
                int col = wn + nf * 8 + r;
                int kb = ks + cq;
                bh[nf][0] = *reinterpret_cast<const unsigned*>(Bsh + col * GST + kb);
                bh[nf][1] = *reinterpret_cast<const unsigned*>(Bsh + col * GST + kb + 8);
                bl[nf][0] = *reinterpret_cast<const unsigned*>(Bsl + col * GST + kb);
                bl[nf][1] = *reinterpret_cast<const unsigned*>(Bsl + col * GST + kb + 8);
            }
            #pragma unroll
            for (int mf = 0; mf < 2; mf++)
                #pragma unroll
                for (int nf = 0; nf < 4; nf++) {
                    mma16816(c[mf][nf], ah[mf], bh[nf]);
                    mma16816(c[mf][nf], ah[mf], bl[nf]);
                    mma16816(c[mf][nf], al[mf], bh[nf]);
                }
        }
        __syncthreads();
    }

    // ---- store ----
    int r = lane >> 2, cq = (lane & 3) * 2;
    #pragma unroll
    for (int mf = 0; mf < 2; mf++) {
        #pragma unroll
        for (int nf = 0; nf < 4; nf++) {
            int row = m0 + wm + mf * 16 + r;
            int col = n0 + wn + nf * 8 + cq;
            float b0 = (bias && col < N) ? bias[col] : 0.f;
            float b1 = (bias && col + 1 < N) ? bias[col + 1] : 0.f;
            if (row < M) {
                if (col < N)     C[(size_t)row * N + col]     = c[mf][nf][0] + b0;
                if (col + 1 < N) C[(size_t)row * N + col + 1] = c[mf][nf][1] + b1;
            }
            if (row + 8 < M) {
                if (col < N)     C[(size_t)(row + 8) * N + col]     = c[mf][nf][2] + b0;
                if (col + 1 < N) C[(size_t)(row + 8) * N + col + 1] = c[mf][nf][3] + b1;
            }
        }
    }
}

// ---------------- GraphNorm ----------------
__global__ void gn_stats_part(const float* __restrict__ x) {
    int g = blockIdx.x;
    int part = blockIdx.y;
    int f = threadIdx.x;
    if (f >= HC) return;
    int s0 = g_start[g], s1 = g_start[g + 1];
    float sum = 0.f, sq = 0.f;
    for (int n = s0 + part; n < s1; n += PARTS) {
        float v = x[(size_t)n * HC + f];
        sum += v;
        sq += v * v;
    }
    atomicAdd(&g_sum[g * HC + f], sum);
    atomicAdd(&g_sq[g * HC + f], sq);
}
__global__ void gn_finalize(const float* __restrict__ gn_ms, int layer) {
    int idx = blockIdx.x * blockDim.x + threadIdx.x;
    if (idx >= G * HC) return;
    int g = idx / HC, f = idx - g * HC;
    float cnt = (float)max(g_start[g + 1] - g_start[g], 1);
    float m = g_sum[idx] / cnt;
    float ms = gn_ms[layer * HC + f];
    float var = g_sq[idx] / cnt + m * m * (ms * ms - 2.f * ms);
    g_mean[idx] = m;
    g_rstd[idx] = 1.f / sqrtf(var + 1e-5f);
}
__global__ void gn_norm_relu(const float* __restrict__ x, float* __restrict__ y,
                             const float* __restrict__ gn_w, const float* __restrict__ gn_b,
                             const float* __restrict__ gn_ms, int layer,
                             const int* __restrict__ batch) {
    int idx = blockIdx.x * blockDim.x + threadIdx.x;
    if (idx >= NN * HC) return;
    int n = idx / HC, f = idx - n * HC;
    int g = batch[n];
    float v = (x[idx] - gn_ms[layer * HC + f] * g_mean[g * HC + f]) * g_rstd[g * HC + f];
    v = v * gn_w[layer * HC + f] + gn_b[layer * HC + f];
    y[idx] = fmaxf(v, 0.f);
}

// ---------------- fused GATv2 attention (online softmax, CSR by dst) ----------------
__global__ __launch_bounds__(256) void attn_fused(
    const float* __restrict__ att, float* __restrict__ io, int addResid) {
    int idx = blockIdx.x * blockDim.x + threadIdx.x;
    if (idx >= NN * H) return;
    int n = idx / H;
    int h = idx - n * H;

    const float* xrp = g_xr + (size_t)n * HC + h * HIDF;
    const float* atp = att + h * HIDF;
    float xr[16], at[16];
    #pragma unroll
    for (int i = 0; i < 4; i++) {
        float4 v = reinterpret_cast<const float4*>(xrp)[i];
        xr[i*4+0] = v.x; xr[i*4+1] = v.y; xr[i*4+2] = v.z; xr[i*4+3] = v.w;
        float4 a = reinterpret_cast<const float4*>(atp)[i];
        at[i*4+0] = a.x; at[i*4+1] = a.y; at[i*4+2] = a.z; at[i*4+3] = a.w;
    }

    float m = -1e30f, den = 0.f;
    float acc[16];
    #pragma unroll
    for (int j = 0; j < 16; j++) acc[j] = 0.f;

    int e0 = g_rowptr[n], e1 = g_rowptr[n + 1];
    for (int e = e0; e < e1; e++) {
        int s = g_csr[e];
        const float4* pl = reinterpret_cast<const float4*>(g_xl + (size_t)s * HC + h * HIDF);
        float xl[16];
        #pragma unroll
        for (int i = 0; i < 4; i++) {
            float4 v = pl[i];
            xl[i*4+0] = v.x; xl[i*4+1] = v.y; xl[i*4+2] = v.z; xl[i*4+3] = v.w;
        }
        float alpha = 0.f;
        #pragma unroll
        for (int j = 0; j < 16; j++) {
            float v = xl[j] + xr[j];
            v = v > 0.f ? v : 0.2f * v;
            alpha += v * at[j];
        }
        if (alpha > m) {
            float rsc = __expf(m - alpha);
            den = den * rsc + 1.f;
            #pragma unroll
            for (int j = 0; j < 16; j++) acc[j] = acc[j] * rsc + xl[j];
            m = alpha;
        } else {
            float ex = __expf(alpha - m);
            den += ex;
            #pragma unroll
            for (int j = 0; j < 16; j++) acc[j] += ex * xl[j];
        }
    }
    float inv = 1.f / (den + 1e-16f);
    float* op = io + (size_t)n * HC + h * HIDF;
    #pragma unroll
    for (int j = 0; j < 16; j++) {
        float base = addResid ? op[j] : 0.f;
        op[j] = base + acc[j] * inv;
    }
}

// ---------------- conv5 head mean + relu ----------------
__global__ void head_mean_relu() {
    int idx = blockIdx.x * blockDim.x + threadIdx.x;
    if (idx >= NN * HIDF) return;
    int n = idx / HIDF, c = idx - n * HIDF;
    float s = 0.f;
    #pragma unroll
    for (int h = 0; h < H; h++) s += g_buf[(size_t)n * HC + h * HIDF + c];
    g_out16[idx] = fmaxf(g_out16[idx] + s * (1.f / (float)H), 0.f);
}

// ---------------- final fused MLP: 16 -> 16 -> 32 -> 10 ----------------
__global__ void mlp(const float* __restrict__ Wo1, const float* __restrict__ bo1,
                    const float* __restrict__ Wo2, const float* __restrict__ bo2,
                    const float* __restrict__ Wc,  const float* __restrict__ bc,
                    float* __restrict__ out) {
    __shared__ float w1[16 * 16], w2[16 * 32], w3[32 * 10], b1[16], b2[32], b3[10];
    int tid = threadIdx.x;
    if (tid < 256) w1[tid] = Wo1[tid];
    for (int t = tid; t < 512; t += blockDim.x) w2[t] = Wo2[t];
    for (int t = tid; t < 320; t += blockDim.x) w3[t] = Wc[t];
    if (tid < 16) b1[tid] = bo1[tid];
    if (tid < 32) b2[tid] = bo2[tid];
    if (tid < 10) b3[tid] = bc[tid];
    __syncthreads();
    int n = blockIdx.x * blockDim.x + tid;
    if (n >= NN) return;
    float a[16];
    #pragma unroll
    for (int i = 0; i < 16; i++) a[i] = g_out16[(size_t)n * 16 + i];
    float t1[16];
    #pragma unroll
    for (int j = 0; j < 16; j++) {
        float acc = b1[j];
        #pragma unroll
        for (int i = 0; i < 16; i++) acc += a[i] * w1[i * 16 + j];
        t1[j] = fmaxf(acc, 0.f);
    }
    float t2[32];
    #pragma unroll
    for (int j = 0; j < 32; j++) {
        float acc = b2[j];
        #pragma unroll
        for (int i = 0; i < 16; i++) acc += t1[i] * w2[i * 32 + j];
        t2[j] = fmaxf(acc, 0.f);
    }
    #pragma unroll
    for (int j = 0; j < 10; j++) {
        float acc = b3[j];
        #pragma unroll
        for (int k = 0; k < 32; k++) acc += t2[k] * w3[k * 10 + j];
        out[(size_t)n * 10 + j] = acc;
    }
}

// ---------------- host launch ----------------
extern "C" void kernel_launch(void* const* d_in, const int* in_sizes, int n_in,
                              void* d_out, int out_size) {
    const float* x        = (const float*)d_in[0];
    const int*   ei       = (const int*)d_in[1];
    const int*   batch    = (const int*)d_in[2];
    const float* W_pre    = (const float*)d_in[3];
    const float* b_pre    = (const float*)d_in[4];
    const float* gn_w     = (const float*)d_in[5];
    const float* gn_b     = (const float*)d_in[6];
    const float* gn_ms    = (const float*)d_in[7];
    const float* conv_Wl  = (const float*)d_in[8];
    const float* conv_Wr  = (const float*)d_in[9];
    const float* conv_att = (const float*)d_in[10];
    const float* conv_b   = (const float*)d_in[11];
    const float* conv_Wres= (const float*)d_in[12];
    const float* c5_Wl    = (const float*)d_in[13];
    const float* c5_Wr    = (const float*)d_in[14];
    const float* c5_att   = (const float*)d_in[15];
    const float* c5_b     = (const float*)d_in[16];
    const float* c5_Wres  = (const float*)d_in[17];
    const float* W_o1     = (const float*)d_in[18];
    const float* b_o1     = (const float*)d_in[19];
    const float* W_o2     = (const float*)d_in[20];
    const float* b_o2     = (const float*)d_in[21];
    const float* W_cls    = (const float*)d_in[22];
    const float* b_cls    = (const float*)d_in[23];
    float* out = (float*)d_out;

    float *p_h, *p_buf, *p_xl, *p_xr, *p_sum, *p_sq, *p_out16;
    __nv_bfloat16 *p_wh, *p_wl;
    int *p_start, *p_deg, *p_rowptr, *p_cursor, *p_bsum, *p_boff;
    cudaGetSymbolAddress((void**)&p_h, g_h);
    cudaGetSymbolAddress((void**)&p_buf, g_buf);
    cudaGetSymbolAddress((void**)&p_xl, g_xl);
    cudaGetSymbolAddress((void**)&p_xr, g_xr);
    cudaGetSymbolAddress((void**)&p_sum, g_sum);
    cudaGetSymbolAddress((void**)&p_sq, g_sq);
    cudaGetSymbolAddress((void**)&p_out16, g_out16);
    cudaGetSymbolAddress((void**)&p_wh, g_wh);
    cudaGetSymbolAddress((void**)&p_wl, g_wl);
    cudaGetSymbolAddress((void**)&p_start, g_start);
    cudaGetSymbolAddress((void**)&p_deg, g_deg);
    cudaGetSymbolAddress((void**)&p_rowptr, g_rowptr);
    cudaGetSymbolAddress((void**)&p_cursor, g_cursor);
    cudaGetSymbolAddress((void**)&p_bsum, g_bsum);
    cudaGetSymbolAddress((void**)&p_boff, g_boff);

    // ---- segment boundaries ----
    cudaMemsetAsync(p_start, 0xFF, (G + 1) * sizeof(int));
    seg_mark<<<(NN + 255) / 256, 256>>>(batch, p_start);
    seg_fix<<<1, 32>>>(p_start);

    // ---- CSR build (by dst, incl self-loops) ----
    const int NBLK = (NN + SCAN_B - 1) / SCAN_B;  // 196
    cudaMemsetAsync(p_deg, 0, NN * sizeof(int));
    deg_count<<<(EP + 255) / 256, 256>>>(ei);
    scan1<<<NBLK, SCAN_B>>>(p_deg, p_rowptr, p_bsum, NN);
    scan1<<<1, SCAN_B>>>(p_bsum, p_boff, nullptr, NBLK);
    scan_add<<<NBLK, SCAN_B>>>(p_rowptr, p_boff, NN);
    set_tail<<<1, 32>>>(p_rowptr);
    cudaMemcpyAsync(p_cursor, p_rowptr, NN * sizeof(int), cudaMemcpyDeviceToDevice);
    csr_scatter<<<(EP + 255) / 256, 256>>>(ei);

    // ---- weight splits ----
    auto split = [&](const float* w, int off, int n) {
        wsplit<<<(n + 255) / 256, 256>>>(w, p_wh + off, p_wl + off, n);
    };
    split(W_pre,    OFF_PRE,   SZ_PRE);
    split(conv_Wl,  OFF_WL,    4 * SZ_W);
    split(conv_Wr,  OFF_WR,    4 * SZ_W);
    split(conv_Wres,OFF_WRES,  4 * SZ_W);
    split(c5_Wl,    OFF_C5L,   SZ_W);
    split(c5_Wr,    OFF_C5R,   SZ_W);
    split(c5_Wres,  OFF_C5RES, SZ_C5RES);

    auto gemm = [&](const float* A, int woff, const float* bias, float* C,
                    int M, int Ncols, int K) {
        dim3 grid((Ncols + GBN - 1) / GBN, (M + GBM - 1) / GBM);
        gemm3x<<<grid, 256>>>(A, p_wh + woff, p_wl + woff, bias, C, M, Ncols, K);
    };
    auto graphnorm = [&](const float* src, float* dst, int layer) {
        cudaMemsetAsync(p_sum, 0, G * HC * sizeof(float));
        cudaMemsetAsync(p_sq, 0, G * HC * sizeof(float));
        dim3 sgrid(G, PARTS);
        gn_stats_part<<<sgrid, 192>>>(src);
        gn_finalize<<<(G * HC + 255) / 256, 256>>>(gn_ms, layer);
        gn_norm_relu<<<(NN * HC + 255) / 256, 256>>>(src, dst, gn_w, gn_b, gn_ms, layer, batch);
    };

    const int attGrid = (NN * H + 255) / 256;

    // ---- pre-layer ----
    gemm(x, OFF_PRE, b_pre, p_buf, NN, HC, IN_F);
    graphnorm(p_buf, p_h, 0);

    // ---- conv layers 1..4 (concat=True) ----
    for (int L = 0; L < 4; L++) {
        gemm(p_h, OFF_WL + L * SZ_W, nullptr, p_xl, NN, HC, HC);
        gemm(p_h, OFF_WR + L * SZ_W, nullptr, p_xr, NN, HC, HC);
        gemm(p_h, OFF_WRES + L * SZ_W, conv_b + L * HC, p_buf, NN, HC, HC);
        attn_fused<<<attGrid, 256>>>(conv_att + L * H * HIDF, p_buf, 1);
        graphnorm(p_buf, p_h, L + 1);
    }

    // ---- conv5 (concat=False -> mean over heads) ----
    gemm(p_h, OFF_C5L, nullptr, p_xl, NN, HC, HC);
    gemm(p_h, OFF_C5R, nullptr, p_xr, NN, HC, HC);
    gemm(p_h, OFF_C5RES, c5_b, p_out16, NN, HIDF, HC);
    attn_fused<<<attGrid, 256>>>(c5_att, p_buf, 0);
    head_mean_relu<<<(NN * HIDF + 255) / 256, 256>>>();

    // ---- final MLP ----
    mlp<<<(NN + 255) / 256, 256>>>(W_o1, b_o1, W_o2, b_o2, W_cls, b_cls, out);
}